// round 5
// baseline (speedup 1.0000x reference)
#include <cuda_runtime.h>
#include <math.h>

#define N_PTS 32768
#define H     64
#define NBLK  128
#define TPB   512          // 2 threads per point, 256 points per block
#define NELEM (N_PTS*3)
#define MAX_STEPS 24

// ---------------- persistent device state (no allocation) ----------------
__device__ volatile int   g_count[MAX_STEPS];
__device__ volatile float g_partials[2][NBLK];

// ---------------- dopri5 tableau ------------------------------------------
__constant__ float cC[7] = { 0.0f, 0.2f, 0.3f, 0.8f, (float)(8.0/9.0), 1.0f, 1.0f };
__constant__ float cA[7][6] = {
    {0,0,0,0,0,0},
    {(float)(1.0/5.0),0,0,0,0,0},
    {(float)(3.0/40.0),(float)(9.0/40.0),0,0,0,0},
    {(float)(44.0/45.0),(float)(-56.0/15.0),(float)(32.0/9.0),0,0,0},
    {(float)(19372.0/6561.0),(float)(-25360.0/2187.0),(float)(64448.0/6561.0),(float)(-212.0/729.0),0,0},
    {(float)(9017.0/3168.0),(float)(-355.0/33.0),(float)(46732.0/5247.0),(float)(49.0/176.0),(float)(-5103.0/18656.0),0},
    {(float)(35.0/384.0),0.0f,(float)(500.0/1113.0),(float)(125.0/192.0),(float)(-2187.0/6784.0),(float)(11.0/84.0)},
};
__constant__ float cB[7] = {
    (float)(35.0/384.0), 0.0f, (float)(500.0/1113.0), (float)(125.0/192.0),
    (float)(-2187.0/6784.0), (float)(11.0/84.0), 0.0f
};
__constant__ float cE[7] = {
    (float)(35.0/384.0 - 5179.0/57600.0),
    0.0f,
    (float)(500.0/1113.0 - 7571.0/16695.0),
    (float)(125.0/192.0 - 393.0/640.0),
    (float)(-2187.0/6784.0 + 92097.0/339200.0),
    (float)(11.0/84.0 - 187.0/2100.0),
    (float)(-1.0/40.0)
};

// ---------------- packed f32x2 helpers (Blackwell FFMA2) ------------------
__device__ __forceinline__ unsigned long long ffma2(unsigned long long a,
                                                    unsigned long long b,
                                                    unsigned long long c)
{
    unsigned long long d;
    asm("fma.rn.f32x2 %0, %1, %2, %3;" : "=l"(d) : "l"(a), "l"(b), "l"(c));
    return d;
}
__device__ __forceinline__ unsigned long long splat2(float x)
{
    unsigned long long d;
    asm("mov.b64 %0, {%1, %1};" : "=l"(d) : "f"(x));
    return d;
}
__device__ __forceinline__ void unpack2(unsigned long long v, float& lo, float& hi)
{
    asm("mov.b64 {%0, %1}, %2;" : "=f"(lo), "=f"(hi) : "l"(v));
}

// ---------------- fast tanh: ex2.approx + rcp.approx + 1 Newton ----------
__device__ __forceinline__ float fast_tanh(float x)
{
    x = fminf(fmaxf(x, -9.0f), 9.0f);
    float e;
    asm("ex2.approx.f32 %0, %1;" : "=f"(e) : "f"(x * 2.8853900817779268f)); // 2*log2(e)
    float d = e + 1.0f;
    float r;
    asm("rcp.approx.f32 %0, %1;" : "=f"(r) : "f"(d));
    r = r * fmaf(-d, r, 2.0f);
    return fmaf(-2.0f, r, 1.0f);
}

// ---------------- MLP eval: split across a lane pair ----------------------
// sub = tid&1. This thread owns neurons [sub*32, sub*32+32) in every layer.
// Returns the FULL output f (identical on both lanes of the pair).
__device__ __forceinline__ float3 mlp_eval_pair(
    const float4* __restrict__ sW1t, const float* __restrict__ sb1,
    const float*  __restrict__ sW2,  const float* __restrict__ sb2,
    const float4* __restrict__ sW3,  const float* __restrict__ sb3,
    int nbase,               // neuron base for this thread (0 or 32)
    int lane,                // lane id within warp
    float t, float x0, float x1, float x2)
{
    // ---- layer 1: my 32 neurons ----
    float h1[H / 2];
#pragma unroll
    for (int j = 0; j < H / 2; j++) {
        float4 w = sW1t[nbase + j];
        float a = fmaf(t, w.w, sb1[nbase + j]);
        a = fmaf(x2, w.z, a);
        a = fmaf(x1, w.y, a);
        a = fmaf(x0, w.x, a);
        h1[j] = fast_tanh(a);
    }

    // ---- layer 2: my 32 output neurons, all 64 k via pair shuffle ----
    unsigned long long acc[H / 4];     // 16 packed pairs = 32 neurons
    {
        const unsigned long long* b2p = (const unsigned long long*)(sb2 + nbase);
#pragma unroll
        for (int p = 0; p < H / 4; p++) acc[p] = b2p[p];
    }

    const int pair_even = lane & ~1;   // even lane of this pair
#pragma unroll
    for (int half = 0; half < 2; half++) {
        const int src = pair_even + half;         // lane that owns h1[half*32 ..]
#pragma unroll
        for (int kk = 0; kk < H / 2; kk++) {
            float hk = __shfl_sync(0xFFFFFFFFu, h1[kk], src);
            unsigned long long hs = splat2(hk);
            const int k = half * (H / 2) + kk;
            const ulonglong2* wrow = (const ulonglong2*)(sW2 + k * H + nbase);
#pragma unroll
            for (int q = 0; q < H / 8; q++) {     // 8 x 16B = 32 neurons
                ulonglong2 w = wrow[q];
                acc[2 * q]     = ffma2(hs, w.x, acc[2 * q]);
                acc[2 * q + 1] = ffma2(hs, w.y, acc[2 * q + 1]);
            }
        }
    }

    // ---- tanh + layer 3 partial ----
    float o0 = 0.0f, o1 = 0.0f, o2 = 0.0f;
#pragma unroll
    for (int p = 0; p < H / 4; p++) {
        float u, v;
        unpack2(acc[p], u, v);
        float ha = fast_tanh(u);
        float hb = fast_tanh(v);
        float4 wa = sW3[nbase + 2 * p];
        float4 wb = sW3[nbase + 2 * p + 1];
        o0 = fmaf(ha, wa.x, o0); o1 = fmaf(ha, wa.y, o1); o2 = fmaf(ha, wa.z, o2);
        o0 = fmaf(hb, wb.x, o0); o1 = fmaf(hb, wb.y, o1); o2 = fmaf(hb, wb.z, o2);
    }
    // combine partials across the pair: f = even_part + odd_part (+ bias)
    // Fixed order (even + odd) so both lanes compute bitwise-identical sums.
    float e0 = __shfl_sync(0xFFFFFFFFu, o0, pair_even);
    float e1 = __shfl_sync(0xFFFFFFFFu, o1, pair_even);
    float e2 = __shfl_sync(0xFFFFFFFFu, o2, pair_even);
    float d0 = __shfl_sync(0xFFFFFFFFu, o0, pair_even + 1);
    float d1 = __shfl_sync(0xFFFFFFFFu, o1, pair_even + 1);
    float d2 = __shfl_sync(0xFFFFFFFFu, o2, pair_even + 1);
    return make_float3(sb3[0] + e0 + d0, sb3[1] + e1 + d1, sb3[2] + e2 + d2);
}

// ---------------- init: reset barrier counters every replay ---------------
__global__ void ode_init_kernel()
{
    int i = threadIdx.x;
    if (i < MAX_STEPS) g_count[i] = 0;
}

// ---------------- persistent fused integrator -----------------------------
__global__ void __launch_bounds__(TPB, 1)
ode_persistent_kernel(const float* __restrict__ yin,
                      const float* __restrict__ W1, const float* __restrict__ b1,
                      const float* __restrict__ W2, const float* __restrict__ b2,
                      const float* __restrict__ W3, const float* __restrict__ b3,
                      float* __restrict__ yout)
{
    __shared__ __align__(16) float4 sW1t[H];
    __shared__ __align__(16) float  sb1[H];
    __shared__ __align__(16) float  sW2[H * H];    // natural [k][j] layout
    __shared__ __align__(16) float  sb2[H];
    __shared__ __align__(16) float4 sW3[H];
    __shared__ __align__(16) float  sb3[4];
    __shared__ float  red[TPB];

    const int tid  = threadIdx.x;
    const int bid  = blockIdx.x;
    const int lane = tid & 31;
    const int sub  = tid & 1;            // which half of the neurons we own
    const int nbase = sub * (H / 2);

    {
        const float4* src = (const float4*)W2;
        float4* dst = (float4*)sW2;
        for (int idx = tid; idx < H * H / 4; idx += TPB) dst[idx] = src[idx];
    }
    if (tid < H) {
        sW1t[tid] = make_float4(W1[0*H + tid], W1[1*H + tid], W1[2*H + tid], W1[3*H + tid]);
        sb1[tid] = b1[tid];
        sb2[tid] = b2[tid];
        sW3[tid] = make_float4(W3[tid*3 + 0], W3[tid*3 + 1], W3[tid*3 + 2], 0.0f);
    }
    if (tid < 3) sb3[tid] = b3[tid];
    __syncthreads();

    const int n = bid * (TPB / 2) + (tid >> 1);   // point index (shared by the pair)
    float y0 = yin[3*n + 0];
    float y1 = yin[3*n + 1];
    float y2 = yin[3*n + 2];

    float t  = 0.0f;
    float dt = 0.05f;

    for (int s = 0; s < MAX_STEPS; s++) {
        const float rem = 1.0f - t;
        if (!(rem > 1e-9f)) break;                 // identical across blocks/threads
        const float dtc = fminf(dt, rem);

        // ---- 7 dopri5 stages (state replicated in both lanes of the pair) ----
        float kb[7][3];
#pragma unroll 1
        for (int i = 0; i < 7; i++) {
            float yi0 = y0, yi1 = y1, yi2 = y2;
            for (int j = 0; j < i; j++) {
                float c = dtc * cA[i][j];
                yi0 += c * kb[j][0];
                yi1 += c * kb[j][1];
                yi2 += c * kb[j][2];
            }
            float3 f = mlp_eval_pair(sW1t, sb1, sW2, sb2, sW3, sb3,
                                     nbase, lane, t + cC[i] * dtc, yi0, yi1, yi2);
            kb[i][0] = f.x; kb[i][1] = f.y; kb[i][2] = f.z;
        }

        float yn0 = y0, yn1 = y1, yn2 = y2;
        float ye0 = 0.0f, ye1 = 0.0f, ye2 = 0.0f;
        for (int i = 0; i < 7; i++) {
            float cb = dtc * cB[i];
            float ce = dtc * cE[i];
            yn0 += cb * kb[i][0]; yn1 += cb * kb[i][1]; yn2 += cb * kb[i][2];
            ye0 += ce * kb[i][0]; ye1 += ce * kb[i][1]; ye2 += ce * kb[i][2];
        }

        // ---- per-point error (count once: even lane only) ----
        float local = 0.0f;
        if (sub == 0) {
            float tol0 = 1e-5f + 1e-5f * fmaxf(fabsf(y0), fabsf(yn0));
            float tol1 = 1e-5f + 1e-5f * fmaxf(fabsf(y1), fabsf(yn1));
            float tol2 = 1e-5f + 1e-5f * fmaxf(fabsf(y2), fabsf(yn2));
            float r0 = ye0 / tol0, r1 = ye1 / tol1, r2 = ye2 / tol2;
            local = r0*r0 + (r1*r1 + r2*r2);
        }
        red[tid] = local;
        __syncthreads();
        for (int sh = TPB / 2; sh > 0; sh >>= 1) {
            if (tid < sh) red[tid] += red[tid + sh];
            __syncthreads();
        }

        // ---- grid barrier: publish partial, arrive, spin ----
        const int buf = s & 1;
        if (tid == 0) {
            g_partials[buf][bid] = red[0];
            __threadfence();
            atomicAdd((int*)&g_count[s], 1);
            while (g_count[s] < NBLK) { }
            __threadfence();
        }
        __syncthreads();

        // ---- redundant deterministic controller in every block ----
        if (tid < NBLK) red[tid] = g_partials[buf][tid];
        __syncthreads();
        for (int sh = NBLK / 2; sh > 0; sh >>= 1) {
            if (tid < sh) red[tid] += red[tid + sh];
            __syncthreads();
        }
        float total = red[0];
        __syncthreads();

        float err = sqrtf(total / (float)NELEM);
        err = fmaxf(err, 1e-10f);
        bool accept = err <= 1.0f;
        float factor = 0.9f * powf(err, -0.2f);
        factor = fminf(fmaxf(factor, 0.2f), 10.0f);
        if (accept) { t += dtc; y0 = yn0; y1 = yn1; y2 = yn2; }
        dt = dtc * factor;
    }

    if (sub == 0) {
        yout[3*n + 0] = y0;
        yout[3*n + 1] = y1;
        yout[3*n + 2] = y2;
    }
}

// ---------------- launch --------------------------------------------------
extern "C" void kernel_launch(void* const* d_in, const int* in_sizes, int n_in,
                              void* d_out, int out_size)
{
    const float* y_in = (const float*)d_in[0];
    const float* W1   = (const float*)d_in[1];
    const float* b1   = (const float*)d_in[2];
    const float* W2   = (const float*)d_in[3];
    const float* b2   = (const float*)d_in[4];
    const float* W3   = (const float*)d_in[5];
    const float* b3   = (const float*)d_in[6];
    float* y = (float*)d_out;

    ode_init_kernel<<<1, 32>>>();
    ode_persistent_kernel<<<NBLK, TPB>>>(y_in, W1, b1, W2, b2, W3, b3, y);
}

// round 7
// speedup vs baseline: 1.6976x; 1.6976x over previous
#include <cuda_runtime.h>
#include <math.h>

#define N_PTS 32768
#define H     64
#define NBLK  128
#define TPB   256
#define NELEM (N_PTS*3)
#define MAX_STEPS 24

// ---------------- persistent device state (no allocation) ----------------
__device__ volatile int   g_count[MAX_STEPS];
__device__ volatile float g_partials[2][NBLK];

// ---------------- dopri5 tableau ------------------------------------------
__constant__ float cC[7] = { 0.0f, 0.2f, 0.3f, 0.8f, (float)(8.0/9.0), 1.0f, 1.0f };
__constant__ float cA[7][6] = {
    {0,0,0,0,0,0},
    {(float)(1.0/5.0),0,0,0,0,0},
    {(float)(3.0/40.0),(float)(9.0/40.0),0,0,0,0},
    {(float)(44.0/45.0),(float)(-56.0/15.0),(float)(32.0/9.0),0,0,0},
    {(float)(19372.0/6561.0),(float)(-25360.0/2187.0),(float)(64448.0/6561.0),(float)(-212.0/729.0),0,0},
    {(float)(9017.0/3168.0),(float)(-355.0/33.0),(float)(46732.0/5247.0),(float)(49.0/176.0),(float)(-5103.0/18656.0),0},
    {(float)(35.0/384.0),0.0f,(float)(500.0/1113.0),(float)(125.0/192.0),(float)(-2187.0/6784.0),(float)(11.0/84.0)},
};
__constant__ float cB[7] = {
    (float)(35.0/384.0), 0.0f, (float)(500.0/1113.0), (float)(125.0/192.0),
    (float)(-2187.0/6784.0), (float)(11.0/84.0), 0.0f
};
__constant__ float cE[7] = {
    (float)(35.0/384.0 - 5179.0/57600.0),
    0.0f,
    (float)(500.0/1113.0 - 7571.0/16695.0),
    (float)(125.0/192.0 - 393.0/640.0),
    (float)(-2187.0/6784.0 + 92097.0/339200.0),
    (float)(11.0/84.0 - 187.0/2100.0),
    (float)(-1.0/40.0)
};

// ---------------- packed f32x2 helpers (Blackwell FFMA2) ------------------
__device__ __forceinline__ unsigned long long ffma2(unsigned long long a,
                                                    unsigned long long b,
                                                    unsigned long long c)
{
    unsigned long long d;
    asm("fma.rn.f32x2 %0, %1, %2, %3;" : "=l"(d) : "l"(a), "l"(b), "l"(c));
    return d;
}
__device__ __forceinline__ unsigned long long splat2(float x)
{
    unsigned long long d;
    asm("mov.b64 %0, {%1, %1};" : "=l"(d) : "f"(x));
    return d;
}
__device__ __forceinline__ void unpack2(unsigned long long v, float& lo, float& hi)
{
    asm("mov.b64 {%0, %1}, %2;" : "=f"(lo), "=f"(hi) : "l"(v));
}

// ---------------- fast tanh: ex2.approx + rcp.approx + 1 Newton ----------
__device__ __forceinline__ float fast_tanh(float x)
{
    x = fminf(fmaxf(x, -9.0f), 9.0f);
    float e;
    asm("ex2.approx.f32 %0, %1;" : "=f"(e) : "f"(x * 2.8853900817779268f)); // 2*log2(e)
    float d = e + 1.0f;
    float r;
    asm("rcp.approx.f32 %0, %1;" : "=f"(r) : "f"(d));
    r = r * fmaf(-d, r, 2.0f);
    return fmaf(-2.0f, r, 1.0f);
}

// ---------------- MLP: x(3)+t -> tanh(64) -> tanh(64) -> 3 ---------------
// Layer 1 FUSED into the layer-2 k-loop: h1[k] computed on demand, never
// stored to an array. 32 packed f32x2 accumulators carry ALL 64 neurons.
__device__ __forceinline__ float3 mlp_eval(
    const float4* __restrict__ sW1t, const float* __restrict__ sb1,
    const float*  __restrict__ sW2,  const float* __restrict__ sb2,
    const float4* __restrict__ sW3,  const float* __restrict__ sb3,
    float t, float x0, float x1, float x2)
{
    unsigned long long acc[H / 2];          // 32 packed pairs = 64 neurons
    {
        const unsigned long long* b2p = (const unsigned long long*)sb2;
#pragma unroll
        for (int p = 0; p < H / 2; p++) acc[p] = b2p[p];
    }

#pragma unroll 4
    for (int k = 0; k < H; k++) {
        // ---- layer-1 neuron k, on the fly ----
        float4 w = sW1t[k];
        float a = fmaf(t, w.w, sb1[k]);
        a = fmaf(x2, w.z, a);
        a = fmaf(x1, w.y, a);
        a = fmaf(x0, w.x, a);
        unsigned long long hs = splat2(fast_tanh(a));

        // ---- layer-2 rank-1 update: acc += h1[k] * W2[k][:] (all 64) ----
        const ulonglong2* wrow = (const ulonglong2*)(sW2 + k * H);
#pragma unroll
        for (int q = 0; q < H / 4; q++) {     // 16 x 16B = full 64-float row
            ulonglong2 wv = wrow[q];
            acc[2 * q]     = ffma2(hs, wv.x, acc[2 * q]);
            acc[2 * q + 1] = ffma2(hs, wv.y, acc[2 * q + 1]);
        }
    }

    // ---- tanh + layer 3 (all 64 hidden neurons) ----
    float o0 = sb3[0], o1 = sb3[1], o2 = sb3[2];
#pragma unroll
    for (int p = 0; p < H / 2; p++) {
        float u, v;
        unpack2(acc[p], u, v);
        float ha = fast_tanh(u);
        float hb = fast_tanh(v);
        float4 wa = sW3[2 * p];
        float4 wb = sW3[2 * p + 1];
        o0 = fmaf(ha, wa.x, o0); o1 = fmaf(ha, wa.y, o1); o2 = fmaf(ha, wa.z, o2);
        o0 = fmaf(hb, wb.x, o0); o1 = fmaf(hb, wb.y, o1); o2 = fmaf(hb, wb.z, o2);
    }
    return make_float3(o0, o1, o2);
}

// ---------------- init: reset barrier counters every replay ---------------
__global__ void ode_init_kernel()
{
    int i = threadIdx.x;
    if (i < MAX_STEPS) g_count[i] = 0;
}

// ---------------- persistent fused integrator -----------------------------
__global__ void __launch_bounds__(TPB, 1)
ode_persistent_kernel(const float* __restrict__ yin,
                      const float* __restrict__ W1, const float* __restrict__ b1,
                      const float* __restrict__ W2, const float* __restrict__ b2,
                      const float* __restrict__ W3, const float* __restrict__ b3,
                      float* __restrict__ yout)
{
    __shared__ __align__(16) float4 sW1t[H];
    __shared__ __align__(16) float  sb1[H];
    __shared__ __align__(16) float  sW2[H * H];    // natural [k][j] layout
    __shared__ __align__(16) float  sb2[H];
    __shared__ __align__(16) float4 sW3[H];
    __shared__ __align__(16) float  sb3[4];
    __shared__ float  red[TPB];

    const int tid = threadIdx.x;
    const int bid = blockIdx.x;

    {
        const float4* src = (const float4*)W2;
        float4* dst = (float4*)sW2;
        for (int idx = tid; idx < H * H / 4; idx += TPB) dst[idx] = src[idx];
    }
    if (tid < H) {
        sW1t[tid] = make_float4(W1[0*H + tid], W1[1*H + tid], W1[2*H + tid], W1[3*H + tid]);
        sb1[tid] = b1[tid];
        sb2[tid] = b2[tid];
        sW3[tid] = make_float4(W3[tid*3 + 0], W3[tid*3 + 1], W3[tid*3 + 2], 0.0f);
    }
    if (tid < 3) sb3[tid] = b3[tid];
    __syncthreads();

    const int n = bid * TPB + tid;
    float y0 = yin[3*n + 0];
    float y1 = yin[3*n + 1];
    float y2 = yin[3*n + 2];

    float t  = 0.0f;
    float dt = 0.05f;

    for (int s = 0; s < MAX_STEPS; s++) {
        const float rem = 1.0f - t;
        if (!(rem > 1e-9f)) break;                 // identical across blocks (deterministic)
        const float dtc = fminf(dt, rem);

        // ---- 7 dopri5 stages ----
        float kb[7][3];
#pragma unroll 1
        for (int i = 0; i < 7; i++) {
            float yi0 = y0, yi1 = y1, yi2 = y2;
            for (int j = 0; j < i; j++) {
                float c = dtc * cA[i][j];
                yi0 += c * kb[j][0];
                yi1 += c * kb[j][1];
                yi2 += c * kb[j][2];
            }
            float3 f = mlp_eval(sW1t, sb1, sW2, sb2, sW3, sb3,
                                t + cC[i] * dtc, yi0, yi1, yi2);
            kb[i][0] = f.x; kb[i][1] = f.y; kb[i][2] = f.z;
        }

        float yn0 = y0, yn1 = y1, yn2 = y2;
        float ye0 = 0.0f, ye1 = 0.0f, ye2 = 0.0f;
        for (int i = 0; i < 7; i++) {
            float cb = dtc * cB[i];
            float ce = dtc * cE[i];
            yn0 += cb * kb[i][0]; yn1 += cb * kb[i][1]; yn2 += cb * kb[i][2];
            ye0 += ce * kb[i][0]; ye1 += ce * kb[i][1]; ye2 += ce * kb[i][2];
        }

        // ---- per-thread error contribution, block tree reduce ----
        float local;
        {
            float tol0 = 1e-5f + 1e-5f * fmaxf(fabsf(y0), fabsf(yn0));
            float tol1 = 1e-5f + 1e-5f * fmaxf(fabsf(y1), fabsf(yn1));
            float tol2 = 1e-5f + 1e-5f * fmaxf(fabsf(y2), fabsf(yn2));
            float r0 = ye0 / tol0, r1 = ye1 / tol1, r2 = ye2 / tol2;
            local = r0*r0 + (r1*r1 + r2*r2);
        }
        red[tid] = local;
        __syncthreads();
        for (int sh = TPB / 2; sh > 0; sh >>= 1) {
            if (tid < sh) red[tid] += red[tid + sh];
            __syncthreads();
        }

        // ---- grid barrier: publish partial, arrive, spin ----
        const int buf = s & 1;
        if (tid == 0) {
            g_partials[buf][bid] = red[0];
            __threadfence();
            atomicAdd((int*)&g_count[s], 1);
            while (g_count[s] < NBLK) { }
            __threadfence();
        }
        __syncthreads();

        // ---- redundant, deterministic controller in every block ----
        if (tid < NBLK) red[tid] = g_partials[buf][tid];
        __syncthreads();
        for (int sh = NBLK / 2; sh > 0; sh >>= 1) {
            if (tid < sh) red[tid] += red[tid + sh];
            __syncthreads();
        }
        float total = red[0];
        __syncthreads();

        float err = sqrtf(total / (float)NELEM);
        err = fmaxf(err, 1e-10f);
        bool accept = err <= 1.0f;
        float factor = 0.9f * powf(err, -0.2f);
        factor = fminf(fmaxf(factor, 0.2f), 10.0f);
        if (accept) { t += dtc; y0 = yn0; y1 = yn1; y2 = yn2; }
        dt = dtc * factor;
    }

    yout[3*n + 0] = y0;
    yout[3*n + 1] = y1;
    yout[3*n + 2] = y2;
}

// ---------------- launch --------------------------------------------------
extern "C" void kernel_launch(void* const* d_in, const int* in_sizes, int n_in,
                              void* d_out, int out_size)
{
    const float* y_in = (const float*)d_in[0];
    const float* W1   = (const float*)d_in[1];
    const float* b1   = (const float*)d_in[2];
    const float* W2   = (const float*)d_in[3];
    const float* b2   = (const float*)d_in[4];
    const float* W3   = (const float*)d_in[5];
    const float* b3   = (const float*)d_in[6];
    float* y = (float*)d_out;

    ode_init_kernel<<<1, 32>>>();
    ode_persistent_kernel<<<NBLK, TPB>>>(y_in, W1, b1, W2, b2, W3, b3, y);
}